// round 1
// baseline (speedup 1.0000x reference)
#include <cuda_runtime.h>
#include <cuda_bf16.h>
#include <math_constants.h>

#define D_IN   2048
#define D_OUT  2048
#define HD     128
#define NG     4
#define HPG    4
#define SEQ    2048
#define KVD    512   /* NG*HD */

// Scratch (no cudaMalloc allowed). Sized for b=2, s=2048 -> M=4096.
__device__ float g_Q[4096 * 2048];
__device__ float g_K[4096 * 512];
__device__ float g_V[4096 * 512];
__device__ float g_C[4096 * 2048];

// ---------------------------------------------------------------------------
// SGEMM: C[M,N] = A[M,K] @ B[K,N] (+ bias). Row-major. BM=BN=128, BK=16,
// 256 threads, 8x8 per thread. Thread columns split as {tx*4, 64+tx*4} so
// LDS.128 B reads are bank-conflict-free per 8-lane phase.
// ---------------------------------------------------------------------------
__global__ __launch_bounds__(256) void sgemm128(
    const float* __restrict__ A, const float* __restrict__ B,
    float* __restrict__ C, const float* __restrict__ bias,
    int M, int N, int K)
{
    __shared__ float As[16][128];   // As[k][m] (transposed)
    __shared__ float Bs[16][128];   // Bs[k][n]

    const int tid = threadIdx.x;
    const int tx = tid & 15, ty = tid >> 4;
    const int m0 = blockIdx.y * 128, n0 = blockIdx.x * 128;

    float acc[8][8];
#pragma unroll
    for (int i = 0; i < 8; i++)
#pragma unroll
        for (int j = 0; j < 8; j++) acc[i][j] = 0.f;

    for (int k0 = 0; k0 < K; k0 += 16) {
        // Load A tile 128x16 -> As[k][m]. 512 float4, 2 per thread.
#pragma unroll
        for (int u = 0; u < 2; u++) {
            int e = tid * 2 + u;
            int r = e >> 2;              // 0..127 (m)
            int c4 = (e & 3) << 2;       // 0,4,8,12 (k)
            float4 v = *(const float4*)(A + (size_t)(m0 + r) * K + k0 + c4);
            As[c4 + 0][r] = v.x;
            As[c4 + 1][r] = v.y;
            As[c4 + 2][r] = v.z;
            As[c4 + 3][r] = v.w;
        }
        // Load B tile 16x128 -> Bs[k][n]. 512 float4, 2 per thread.
#pragma unroll
        for (int u = 0; u < 2; u++) {
            int e = tid * 2 + u;
            int r = e >> 5;              // 0..15 (k)
            int c = (e & 31) << 2;       // 0..124 (n)
            *(float4*)(&Bs[r][c]) = *(const float4*)(B + (size_t)(k0 + r) * N + n0 + c);
        }
        __syncthreads();

#pragma unroll
        for (int k = 0; k < 16; k++) {
            float a[8], b[8];
            *(float4*)&a[0] = *(float4*)&As[k][ty * 8];
            *(float4*)&a[4] = *(float4*)&As[k][ty * 8 + 4];
            *(float4*)&b[0] = *(float4*)&Bs[k][tx * 4];
            *(float4*)&b[4] = *(float4*)&Bs[k][64 + tx * 4];
#pragma unroll
            for (int i = 0; i < 8; i++)
#pragma unroll
                for (int j = 0; j < 8; j++)
                    acc[i][j] = fmaf(a[i], b[j], acc[i][j]);
        }
        __syncthreads();
    }

#pragma unroll
    for (int i = 0; i < 8; i++) {
        int gr = m0 + ty * 8 + i;
        int gc0 = n0 + tx * 4;
        int gc1 = n0 + 64 + tx * 4;
        float4 v0 = make_float4(acc[i][0], acc[i][1], acc[i][2], acc[i][3]);
        float4 v1 = make_float4(acc[i][4], acc[i][5], acc[i][6], acc[i][7]);
        if (bias) {
            float4 b0 = *(const float4*)(bias + gc0);
            float4 b1 = *(const float4*)(bias + gc1);
            v0.x += b0.x; v0.y += b0.y; v0.z += b0.z; v0.w += b0.w;
            v1.x += b1.x; v1.y += b1.y; v1.z += b1.z; v1.w += b1.w;
        }
        *(float4*)(C + (size_t)gr * N + gc0) = v0;
        *(float4*)(C + (size_t)gr * N + gc1) = v1;
    }
}

// ---------------------------------------------------------------------------
// Flash-attention (causal, grouped). One block = one (batch, group, head) x
// 64-row Q chunk. 256 threads; thread (ty,tx): S-tile 4x4 rows ty*4 cols tx*4,
// PV output rows ty*4, cols {tx*4, 64+tx*4}.
// K smem is swizzled (float4 group g stored at g ^ ((row>>2)&7)) so the
// QK^T inner loop's K reads are conflict-free.
// ---------------------------------------------------------------------------
#define ATTN_SMEM ((64 * 128 * 3 + 64 * 68 + 64 * 16 * 2) * 4)

__global__ __launch_bounds__(256) void attn_kernel(
    const float* __restrict__ Q, const float* __restrict__ K,
    const float* __restrict__ V, float* __restrict__ C)
{
    extern __shared__ float sm[];
    float* Qs   = sm;                    // [64][128]
    float* Ks   = Qs + 64 * 128;         // [64][128] swizzled
    float* Vs   = Ks + 64 * 128;         // [64][128]
    float* Ps   = Vs + 64 * 128;         // [64][68]
    float* redA = Ps + 64 * 68;          // [64][16]
    float* redB = redA + 64 * 16;        // [64][16]

    const int tid = threadIdx.x;
    const int tx = tid & 15, ty = tid >> 4;
    const int ty4 = ty * 4, tx4 = tx * 4;
    const int qc = blockIdx.x;
    const int hh = blockIdx.y;
    const int bi = hh >> 4;
    const int gi = (hh >> 2) & 3;
    const int hi = hh & 3;
    const int qcol = (gi * HPG + hi) * HD;
    const int kcol = gi * HD;
    const size_t rowbase = (size_t)bi * SEQ;
    const int qbase = qc * 64;
    const float scale = 0.08838834764831845f;   // 1/sqrt(128)

    // Load Q tile [64 x 128]
    for (int i = tid; i < 64 * 32; i += 256) {
        int r = i >> 5, c4 = (i & 31) << 2;
        *(float4*)&Qs[r * 128 + c4] =
            *(const float4*)(Q + (rowbase + qbase + r) * D_OUT + qcol + c4);
    }

    float acc[4][8];
#pragma unroll
    for (int i = 0; i < 4; i++)
#pragma unroll
        for (int j = 0; j < 8; j++) acc[i][j] = 0.f;
    float m_r[4], l_r[4], al[4];
#pragma unroll
    for (int i = 0; i < 4; i++) { m_r[i] = -CUDART_INF_F; l_r[i] = 0.f; }

    for (int j = 0; j <= qc; ++j) {
        const int kbase = j * 64;
        __syncthreads();   // protects Qs (1st iter) and Ks/Vs/Ps/red (later)

        // Load K (swizzled) and V tiles [64 x 128]
        for (int i = tid; i < 64 * 32; i += 256) {
            int r = i >> 5, g = i & 31;
            int gk = g ^ ((r >> 2) & 7);
            const float* krow = K + (rowbase + kbase + r) * KVD + kcol;
            const float* vrow = V + (rowbase + kbase + r) * KVD + kcol;
            *(float4*)&Ks[r * 128 + gk * 4] = *(const float4*)(krow + g * 4);
            *(float4*)&Vs[r * 128 + g * 4]  = *(const float4*)(vrow + g * 4);
        }
        __syncthreads();

        // S = Q @ K^T  (4x4 per thread over hd=128)
        float s_[4][4];
#pragma unroll
        for (int i = 0; i < 4; i++)
#pragma unroll
            for (int jj = 0; jj < 4; jj++) s_[i][jj] = 0.f;

#pragma unroll 4
        for (int kk = 0; kk < 128; kk += 4) {
            float4 a0 = *(float4*)&Qs[(ty4 + 0) * 128 + kk];
            float4 a1 = *(float4*)&Qs[(ty4 + 1) * 128 + kk];
            float4 a2 = *(float4*)&Qs[(ty4 + 2) * 128 + kk];
            float4 a3 = *(float4*)&Qs[(ty4 + 3) * 128 + kk];
            int gk = (((kk >> 2) ^ (tx & 7)) << 2);
            float4 b0 = *(float4*)&Ks[(tx4 + 0) * 128 + gk];
            float4 b1 = *(float4*)&Ks[(tx4 + 1) * 128 + gk];
            float4 b2 = *(float4*)&Ks[(tx4 + 2) * 128 + gk];
            float4 b3 = *(float4*)&Ks[(tx4 + 3) * 128 + gk];
            float4 A4[4] = {a0, a1, a2, a3};
            float4 B4[4] = {b0, b1, b2, b3};
#pragma unroll
            for (int i = 0; i < 4; i++)
#pragma unroll
                for (int jj = 0; jj < 4; jj++) {
                    s_[i][jj] = fmaf(A4[i].x, B4[jj].x, s_[i][jj]);
                    s_[i][jj] = fmaf(A4[i].y, B4[jj].y, s_[i][jj]);
                    s_[i][jj] = fmaf(A4[i].z, B4[jj].z, s_[i][jj]);
                    s_[i][jj] = fmaf(A4[i].w, B4[jj].w, s_[i][jj]);
                }
        }

        // Scale + causal mask + per-thread row max
        const bool diag = (j == qc);
#pragma unroll
        for (int i = 0; i < 4; i++) {
            float mx = -CUDART_INF_F;
#pragma unroll
            for (int jj = 0; jj < 4; jj++) {
                float v = s_[i][jj] * scale;
                if (diag && (kbase + tx4 + jj > qbase + ty4 + i)) v = -CUDART_INF_F;
                s_[i][jj] = v;
                mx = fmaxf(mx, v);
            }
            redA[(ty4 + i) * 16 + tx] = mx;
        }
        __syncthreads();

        // Online softmax update
#pragma unroll
        for (int i = 0; i < 4; i++) {
            float mx = -CUDART_INF_F;
#pragma unroll
            for (int t = 0; t < 16; t++) mx = fmaxf(mx, redA[(ty4 + i) * 16 + t]);
            float nm = fmaxf(m_r[i], mx);
            al[i] = __expf(m_r[i] - nm);
            m_r[i] = nm;
            float p0 = __expf(s_[i][0] - nm);
            float p1 = __expf(s_[i][1] - nm);
            float p2 = __expf(s_[i][2] - nm);
            float p3 = __expf(s_[i][3] - nm);
            redB[(ty4 + i) * 16 + tx] = (p0 + p1) + (p2 + p3);
            *(float4*)&Ps[(ty4 + i) * 68 + tx4] = make_float4(p0, p1, p2, p3);
#pragma unroll
            for (int jj = 0; jj < 8; jj++) acc[i][jj] *= al[i];
        }
        __syncthreads();

#pragma unroll
        for (int i = 0; i < 4; i++) {
            float ssum = 0.f;
#pragma unroll
            for (int t = 0; t < 16; t++) ssum += redB[(ty4 + i) * 16 + t];
            l_r[i] = l_r[i] * al[i] + ssum;
        }

        // acc += P @ V
#pragma unroll 2
        for (int kk = 0; kk < 64; kk += 4) {
            float p_[4][4];
#pragma unroll
            for (int i = 0; i < 4; i++)
                *(float4*)&p_[i][0] = *(float4*)&Ps[(ty4 + i) * 68 + kk];
#pragma unroll
            for (int t = 0; t < 4; t++) {
                float4 va = *(float4*)&Vs[(kk + t) * 128 + tx4];
                float4 vb = *(float4*)&Vs[(kk + t) * 128 + 64 + tx4];
#pragma unroll
                for (int i = 0; i < 4; i++) {
                    float p = p_[i][t];
                    acc[i][0] = fmaf(p, va.x, acc[i][0]);
                    acc[i][1] = fmaf(p, va.y, acc[i][1]);
                    acc[i][2] = fmaf(p, va.z, acc[i][2]);
                    acc[i][3] = fmaf(p, va.w, acc[i][3]);
                    acc[i][4] = fmaf(p, vb.x, acc[i][4]);
                    acc[i][5] = fmaf(p, vb.y, acc[i][5]);
                    acc[i][6] = fmaf(p, vb.z, acc[i][6]);
                    acc[i][7] = fmaf(p, vb.w, acc[i][7]);
                }
            }
        }
    }

    // Epilogue: normalize and store ctx
#pragma unroll
    for (int i = 0; i < 4; i++) {
        float inv = 1.f / l_r[i];
        size_t base = (rowbase + qbase + ty4 + i) * (size_t)D_OUT + qcol;
        float4 v0 = make_float4(acc[i][0] * inv, acc[i][1] * inv,
                                acc[i][2] * inv, acc[i][3] * inv);
        float4 v1 = make_float4(acc[i][4] * inv, acc[i][5] * inv,
                                acc[i][6] * inv, acc[i][7] * inv);
        *(float4*)(C + base + tx4)      = v0;
        *(float4*)(C + base + 64 + tx4) = v1;
    }
}

// ---------------------------------------------------------------------------
extern "C" void kernel_launch(void* const* d_in, const int* in_sizes, int n_in,
                              void* d_out, int out_size)
{
    const float* x  = (const float*)d_in[0];
    const float* Wq = (const float*)d_in[1];
    const float* Wk = (const float*)d_in[2];
    const float* Wv = (const float*)d_in[3];
    const float* Wo = (const float*)d_in[4];
    const float* bo = (const float*)d_in[5];

    const int M = in_sizes[0] / D_IN;   // b*s = 4096
    const int B = M / SEQ;              // 2

    float *Qp, *Kp, *Vp, *Cp;
    cudaGetSymbolAddress((void**)&Qp, g_Q);
    cudaGetSymbolAddress((void**)&Kp, g_K);
    cudaGetSymbolAddress((void**)&Vp, g_V);
    cudaGetSymbolAddress((void**)&Cp, g_C);

    cudaFuncSetAttribute(attn_kernel,
                         cudaFuncAttributeMaxDynamicSharedMemorySize, ATTN_SMEM);

    dim3 blk(256);
    sgemm128<<<dim3(D_OUT / 128, M / 128), blk>>>(x, Wq, Qp, nullptr, M, D_OUT, D_IN);
    sgemm128<<<dim3(KVD   / 128, M / 128), blk>>>(x, Wk, Kp, nullptr, M, KVD,   D_IN);
    sgemm128<<<dim3(KVD   / 128, M / 128), blk>>>(x, Wv, Vp, nullptr, M, KVD,   D_IN);
    attn_kernel<<<dim3(SEQ / 64, B * 16), blk, ATTN_SMEM>>>(Qp, Kp, Vp, Cp);
    sgemm128<<<dim3(D_OUT / 128, M / 128), blk>>>(Cp, Wo, (float*)d_out, bo, M, D_OUT, D_OUT);
}

// round 3
// speedup vs baseline: 4.5603x; 4.5603x over previous
#include <cuda_runtime.h>
#include <cuda_bf16.h>
#include <math_constants.h>
#include <cstdint>

#define D_IN   2048
#define D_OUT  2048
#define HD     128
#define NG     4
#define HPG    4
#define SEQ    2048
#define KVD    512   /* NG*HD */

// ---------------- scratch (no cudaMalloc allowed) ----------------
__device__ float g_Q[4096 * 2048];
__device__ float g_K[4096 * 512];
__device__ float g_V[4096 * 512];
__device__ float g_C[4096 * 2048];

// ---------------- helpers ----------------
__device__ __forceinline__ uint32_t f2tf(float x) {
    uint32_t u;
    asm("cvt.rna.tf32.f32 %0, %1;" : "=r"(u) : "f"(x));
    return u;
}
__device__ __forceinline__ float tf32r(float x) { return __uint_as_float(f2tf(x)); }

__device__ __forceinline__ void mma_tf32(float* d, const uint32_t* a, const uint32_t* b) {
    asm volatile(
        "mma.sync.aligned.m16n8k8.row.col.f32.tf32.tf32.f32 "
        "{%0,%1,%2,%3}, {%4,%5,%6,%7}, {%8,%9}, {%0,%1,%2,%3};"
        : "+f"(d[0]), "+f"(d[1]), "+f"(d[2]), "+f"(d[3])
        : "r"(a[0]), "r"(a[1]), "r"(a[2]), "r"(a[3]), "r"(b[0]), "r"(b[1]));
}

__device__ __forceinline__ uint32_t smem_u32(const void* p) {
    uint32_t a;
    asm("{ .reg .u64 t; cvta.to.shared.u64 t, %1; cvt.u32.u64 %0, t; }" : "=r"(a) : "l"(p));
    return a;
}
#define CP_ASYNC16(dst, src) \
    asm volatile("cp.async.cg.shared.global [%0], [%1], 16;" :: "r"(dst), "l"(src) : "memory")
#define CP_COMMIT() asm volatile("cp.async.commit_group;" ::: "memory")
#define CP_WAIT2()  asm volatile("cp.async.wait_group 2;" ::: "memory")

// ---------------- tf32 mma GEMM ----------------
// C[M,N] = A[M,K] @ B[K,N] (+bias). B fragment is col-major -> B used directly.
#define GBM 128
#define GBN 128
#define GBK 32
#define APAD 4
#define BPAD 8
#define AS_F (GBM * (GBK + APAD))     /* 128*36 = 4608 floats */
#define BS_F (GBK * (GBN + BPAD))     /* 32*136 = 4352 floats */
#define STG_F (AS_F + BS_F)           /* 8960 floats */
#define GEMM_SMEM (3 * STG_F * 4)     /* 107520 B */

__global__ __launch_bounds__(256, 1) void mma_gemm(
    const float* __restrict__ A, const float* __restrict__ B,
    float* __restrict__ C, const float* __restrict__ bias,
    int M, int N, int K)
{
    extern __shared__ float smg[];
    const int tid = threadIdx.x;
    const int wid = tid >> 5;
    const int l = tid & 31;
    const int m0 = blockIdx.y * GBM, n0 = blockIdx.x * GBN;
    const int wm = (wid & 1) * 64;
    const int wn = (wid >> 1) * 32;
    const int kiters = K / GBK;

    const uint32_t smbase = smem_u32(smg);

    float acc[4][4][4];
#pragma unroll
    for (int i = 0; i < 4; i++)
#pragma unroll
        for (int j = 0; j < 4; j++)
#pragma unroll
            for (int r = 0; r < 4; r++) acc[i][j][r] = 0.f;

#define G_LOAD_STAGE(s, kc) do {                                                  \
        uint32_t _ab = smbase + (s) * (STG_F * 4);                                \
        uint32_t _bb = _ab + AS_F * 4;                                            \
        _Pragma("unroll")                                                         \
        for (int _i = 0; _i < 4; _i++) {                                          \
            int _e = tid + _i * 256;                                              \
            int _m = _e >> 3, _kq = _e & 7;                                       \
            CP_ASYNC16(_ab + (_m * (GBK + APAD) + _kq * 4) * 4,                   \
                (const void*)(A + (size_t)(m0 + _m) * K + (kc) * GBK + _kq * 4)); \
        }                                                                         \
        _Pragma("unroll")                                                         \
        for (int _i = 0; _i < 4; _i++) {                                          \
            int _e = tid + _i * 256;                                              \
            int _r = _e >> 5, _cq = _e & 31;                                      \
            CP_ASYNC16(_bb + (_r * (GBN + BPAD) + _cq * 4) * 4,                   \
                (const void*)(B + (size_t)((kc) * GBK + _r) * N + n0 + _cq * 4)); \
        }                                                                         \
    } while (0)

    G_LOAD_STAGE(0, 0); CP_COMMIT();
    G_LOAD_STAGE(1, 1); CP_COMMIT();

    for (int it = 0; it < kiters; it++) {
        const int s = it % 3;
        const int j = it + 2;
        if (j < kiters) G_LOAD_STAGE(j % 3, j);
        CP_COMMIT();
        CP_WAIT2();
        __syncthreads();

        const float* As = smg + s * STG_F;
        const float* Bs = As + AS_F;

#pragma unroll
        for (int ks = 0; ks < 4; ks++) {
            const int k8 = ks * 8;
            uint32_t af[4][4], bf[4][2];
#pragma unroll
            for (int mf = 0; mf < 4; mf++) {
                const float* p = As + (wm + mf * 16 + (l >> 2)) * (GBK + APAD) + k8 + (l & 3);
                af[mf][0] = f2tf(p[0]);
                af[mf][1] = f2tf(p[8 * (GBK + APAD)]);
                af[mf][2] = f2tf(p[4]);
                af[mf][3] = f2tf(p[8 * (GBK + APAD) + 4]);
            }
#pragma unroll
            for (int nf = 0; nf < 4; nf++) {
                const float* p = Bs + (k8 + (l & 3)) * (GBN + BPAD) + wn + nf * 8 + (l >> 2);
                bf[nf][0] = f2tf(p[0]);
                bf[nf][1] = f2tf(p[4 * (GBN + BPAD)]);
            }
#pragma unroll
            for (int mf = 0; mf < 4; mf++)
#pragma unroll
                for (int nf = 0; nf < 4; nf++)
                    mma_tf32(acc[mf][nf], af[mf], bf[nf]);
        }
        __syncthreads();
    }

    // epilogue
#pragma unroll
    for (int mf = 0; mf < 4; mf++) {
        const int row = m0 + wm + mf * 16 + (l >> 2);
#pragma unroll
        for (int nf = 0; nf < 4; nf++) {
            const int col = n0 + wn + nf * 8 + 2 * (l & 3);
            float2 v0 = make_float2(acc[mf][nf][0], acc[mf][nf][1]);
            float2 v1 = make_float2(acc[mf][nf][2], acc[mf][nf][3]);
            if (bias) {
                float2 b = *(const float2*)(bias + col);
                v0.x += b.x; v0.y += b.y;
                v1.x += b.x; v1.y += b.y;
            }
            *(float2*)(C + (size_t)row * N + col) = v0;
            *(float2*)(C + (size_t)(row + 8) * N + col) = v1;
        }
    }
#undef G_LOAD_STAGE
}

// ---------------- tf32 mma flash-attention ----------------
// 128 threads (4 warps). CTA: one (batch, head) x 64 q-rows; warp: 16 q-rows.
#define QPAD 4
#define VPAD 8
#define QS_F (64 * (128 + QPAD))   /* 8448 */
#define KS_F (64 * (128 + QPAD))   /* 8448 */
#define VS_F (64 * (128 + VPAD))   /* 8704 */
#define PS_F (4 * 16 * 72)         /* 4608 */
#define ATTN_SMEM ((QS_F + KS_F + VS_F + PS_F) * 4)

__global__ __launch_bounds__(128, 1) void attn_mma(
    const float* __restrict__ Q, const float* __restrict__ K,
    const float* __restrict__ V, float* __restrict__ C)
{
    extern __shared__ float sm[];
    float* Qs = sm;                 // [64][132]
    float* Ks = Qs + QS_F;          // [64][132]
    float* Vs = Ks + KS_F;          // [64][136]
    float* Ps = Vs + VS_F;          // [4][16][72]

    const int tid = threadIdx.x;
    const int wid = tid >> 5;
    const int l = tid & 31;
    const int wq = wid * 16;

    const int qc = blockIdx.x;
    const int hh = blockIdx.y;
    const int bi = hh >> 4;
    const int gi = (hh >> 2) & 3;
    const int hi = hh & 3;
    const int qcol = (gi * HPG + hi) * HD;
    const int kcol = gi * HD;
    const size_t rowbase = (size_t)bi * SEQ;
    const int qbase = qc * 64;
    const float scale = 0.08838834764831845f;   // 1/sqrt(128)

    // Q tile (scale folded, tf32-rounded)
    for (int i = tid; i < 64 * 32; i += 128) {
        int r = i >> 5, c4 = (i & 31) << 2;
        float4 v = *(const float4*)(Q + (rowbase + qbase + r) * D_OUT + qcol + c4);
        float* d = Qs + r * (128 + QPAD) + c4;
        d[0] = tf32r(v.x * scale); d[1] = tf32r(v.y * scale);
        d[2] = tf32r(v.z * scale); d[3] = tf32r(v.w * scale);
    }

    float o[16][4];
#pragma unroll
    for (int i = 0; i < 16; i++)
#pragma unroll
        for (int r = 0; r < 4; r++) o[i][r] = 0.f;
    float m0 = -CUDART_INF_F, m1 = -CUDART_INF_F, l0 = 0.f, l1 = 0.f;

    const int gr0 = qbase + wq + (l >> 2);
    const int gr1 = gr0 + 8;
    float* myP = Ps + wq * 72;

    for (int j = 0; j <= qc; ++j) {
        const int kbase = j * 64;
        __syncthreads();
        // K/V tiles (tf32-rounded)
        for (int i = tid; i < 64 * 32; i += 128) {
            int r = i >> 5, c4 = (i & 31) << 2;
            float4 kv = *(const float4*)(K + (rowbase + kbase + r) * KVD + kcol + c4);
            float4 vv = *(const float4*)(V + (rowbase + kbase + r) * KVD + kcol + c4);
            float* dk = Ks + r * (128 + QPAD) + c4;
            dk[0] = tf32r(kv.x); dk[1] = tf32r(kv.y); dk[2] = tf32r(kv.z); dk[3] = tf32r(kv.w);
            float* dv = Vs + r * (128 + VPAD) + c4;
            dv[0] = tf32r(vv.x); dv[1] = tf32r(vv.y); dv[2] = tf32r(vv.z); dv[3] = tf32r(vv.w);
        }
        __syncthreads();

        // S = Q @ K^T : per warp 16x64
        float s[8][4];
#pragma unroll
        for (int nf = 0; nf < 8; nf++)
#pragma unroll
            for (int r = 0; r < 4; r++) s[nf][r] = 0.f;

#pragma unroll
        for (int kf = 0; kf < 16; kf++) {
            const int kd = kf * 8;
            uint32_t a[4];
            const float* qp = Qs + (wq + (l >> 2)) * (128 + QPAD) + kd + (l & 3);
            a[0] = __float_as_uint(qp[0]);
            a[1] = __float_as_uint(qp[8 * (128 + QPAD)]);
            a[2] = __float_as_uint(qp[4]);
            a[3] = __float_as_uint(qp[8 * (128 + QPAD) + 4]);
#pragma unroll
            for (int nf = 0; nf < 8; nf++) {
                uint32_t b[2];
                const float* kp = Ks + (nf * 8 + (l >> 2)) * (128 + QPAD) + kd + (l & 3);
                b[0] = __float_as_uint(kp[0]);
                b[1] = __float_as_uint(kp[4]);
                mma_tf32(s[nf], a, b);
            }
        }

        // causal mask (diag tile only) + row max
        const bool diag = (j == qc);
        float mx0 = -CUDART_INF_F, mx1 = -CUDART_INF_F;
#pragma unroll
        for (int nf = 0; nf < 8; nf++) {
            if (diag) {
                const int c0 = kbase + nf * 8 + 2 * (l & 3);
                if (c0 > gr0)     s[nf][0] = -CUDART_INF_F;
                if (c0 + 1 > gr0) s[nf][1] = -CUDART_INF_F;
                if (c0 > gr1)     s[nf][2] = -CUDART_INF_F;
                if (c0 + 1 > gr1) s[nf][3] = -CUDART_INF_F;
            }
            mx0 = fmaxf(mx0, fmaxf(s[nf][0], s[nf][1]));
            mx1 = fmaxf(mx1, fmaxf(s[nf][2], s[nf][3]));
        }
#pragma unroll
        for (int msk = 1; msk < 4; msk <<= 1) {
            mx0 = fmaxf(mx0, __shfl_xor_sync(0xffffffffu, mx0, msk));
            mx1 = fmaxf(mx1, __shfl_xor_sync(0xffffffffu, mx1, msk));
        }
        const float nm0 = fmaxf(m0, mx0);
        const float nm1 = fmaxf(m1, mx1);
        const float al0 = __expf(m0 - nm0);
        const float al1 = __expf(m1 - nm1);
        m0 = nm0; m1 = nm1;

        float sm0 = 0.f, sm1 = 0.f;
#pragma unroll
        for (int nf = 0; nf < 8; nf++) {
            float p0 = __expf(s[nf][0] - nm0);
            float p1 = __expf(s[nf][1] - nm0);
            float p2 = __expf(s[nf][2] - nm1);
            float p3 = __expf(s[nf][3] - nm1);
            sm0 += p0 + p1; sm1 += p2 + p3;
            float* pp = myP + (l >> 2) * 72 + nf * 8 + 2 * (l & 3);
            pp[0] = tf32r(p0); pp[1] = tf32r(p1);
            pp[8 * 72] = tf32r(p2); pp[8 * 72 + 1] = tf32r(p3);
        }
#pragma unroll
        for (int msk = 1; msk < 4; msk <<= 1) {
            sm0 += __shfl_xor_sync(0xffffffffu, sm0, msk);
            sm1 += __shfl_xor_sync(0xffffffffu, sm1, msk);
        }
        l0 = l0 * al0 + sm0;
        l1 = l1 * al1 + sm1;

        // rescale O
#pragma unroll
        for (int nf = 0; nf < 16; nf++) {
            o[nf][0] *= al0; o[nf][1] *= al0;
            o[nf][2] *= al1; o[nf][3] *= al1;
        }
        __syncwarp();

        // O += P @ V : per warp 16x128, k over 64 keys
#pragma unroll
        for (int kf = 0; kf < 8; kf++) {
            uint32_t a[4];
            const float* pp = myP + (l >> 2) * 72 + kf * 8 + (l & 3);
            a[0] = __float_as_uint(pp[0]);
            a[1] = __float_as_uint(pp[8 * 72]);
            a[2] = __float_as_uint(pp[4]);
            a[3] = __float_as_uint(pp[8 * 72 + 4]);
#pragma unroll
            for (int nf = 0; nf < 16; nf++) {
                uint32_t b[2];
                const float* vp = Vs + (kf * 8 + (l & 3)) * (128 + VPAD) + nf * 8 + (l >> 2);
                b[0] = __float_as_uint(vp[0]);
                b[1] = __float_as_uint(vp[4 * (128 + VPAD)]);
                mma_tf32(o[nf], a, b);
            }
        }
    }

    // epilogue
    const float inv0 = 1.f / l0, inv1 = 1.f / l1;
    const size_t r0 = rowbase + gr0;
    const size_t r1 = rowbase + gr1;
#pragma unroll
    for (int nf = 0; nf < 16; nf++) {
        const int col = qcol + nf * 8 + 2 * (l & 3);
        *(float2*)(C + r0 * D_OUT + col) = make_float2(o[nf][0] * inv0, o[nf][1] * inv0);
        *(float2*)(C + r1 * D_OUT + col) = make_float2(o[nf][2] * inv1, o[nf][3] * inv1);
    }
}

// ---------------------------------------------------------------------------
extern "C" void kernel_launch(void* const* d_in, const int* in_sizes, int n_in,
                              void* d_out, int out_size)
{
    const float* x  = (const float*)d_in[0];
    const float* Wq = (const float*)d_in[1];
    const float* Wk = (const float*)d_in[2];
    const float* Wv = (const float*)d_in[3];
    const float* Wo = (const float*)d_in[4];
    const float* bo = (const float*)d_in[5];

    const int M = in_sizes[0] / D_IN;   // 4096
    const int B = M / SEQ;              // 2

    float *Qp, *Kp, *Vp, *Cp;
    cudaGetSymbolAddress((void**)&Qp, g_Q);
    cudaGetSymbolAddress((void**)&Kp, g_K);
    cudaGetSymbolAddress((void**)&Vp, g_V);
    cudaGetSymbolAddress((void**)&Cp, g_C);

    cudaFuncSetAttribute(mma_gemm,
                         cudaFuncAttributeMaxDynamicSharedMemorySize, GEMM_SMEM);
    cudaFuncSetAttribute(attn_mma,
                         cudaFuncAttributeMaxDynamicSharedMemorySize, ATTN_SMEM);

    mma_gemm<<<dim3(D_OUT / GBN, M / GBM), 256, GEMM_SMEM>>>(x, Wq, Qp, nullptr, M, D_OUT, D_IN);
    mma_gemm<<<dim3(KVD   / GBN, M / GBM), 256, GEMM_SMEM>>>(x, Wk, Kp, nullptr, M, KVD,   D_IN);
    mma_gemm<<<dim3(KVD   / GBN, M / GBM), 256, GEMM_SMEM>>>(x, Wv, Vp, nullptr, M, KVD,   D_IN);

    attn_mma<<<dim3(SEQ / 64, B * 16), 128, ATTN_SMEM>>>(Qp, Kp, Vp, Cp);

    mma_gemm<<<dim3(D_OUT / GBN, M / GBM), 256, GEMM_SMEM>>>(Cp, Wo, (float*)d_out, bo, M, D_OUT, D_OUT);
}

// round 4
// speedup vs baseline: 5.8538x; 1.2837x over previous
#include <cuda_runtime.h>
#include <cuda_bf16.h>
#include <math_constants.h>
#include <cstdint>

#define D_IN   2048
#define D_OUT  2048
#define HD     128
#define NG     4
#define HPG    4
#define SEQ    2048
#define KVD    1024   /* fused K|V buffer width */

// ---------------- scratch (no cudaMalloc allowed) ----------------
__device__ float g_X [4096 * 2048];   // x, tf32-rounded
__device__ float g_Wq[2048 * 2048];   // weights, tf32-rounded
__device__ float g_Wk[2048 * 512];
__device__ float g_Wv[2048 * 512];
__device__ float g_Wo[2048 * 2048];
__device__ float g_Q [4096 * 2048];   // q proj, scaled + tf32
__device__ float g_KV[4096 * 1024];   // [K | V], tf32
__device__ float g_C [4096 * 2048];   // ctx, tf32

// ---------------- helpers ----------------
__device__ __forceinline__ uint32_t f2tf(float x) {
    uint32_t u;
    asm("cvt.rna.tf32.f32 %0, %1;" : "=r"(u) : "f"(x));
    return u;
}
__device__ __forceinline__ float tf32r(float x) { return __uint_as_float(f2tf(x)); }

__device__ __forceinline__ void mma_tf32(float* d, const uint32_t* a, const uint32_t* b) {
    asm volatile(
        "mma.sync.aligned.m16n8k8.row.col.f32.tf32.tf32.f32 "
        "{%0,%1,%2,%3}, {%4,%5,%6,%7}, {%8,%9}, {%0,%1,%2,%3};"
        : "+f"(d[0]), "+f"(d[1]), "+f"(d[2]), "+f"(d[3])
        : "r"(a[0]), "r"(a[1]), "r"(a[2]), "r"(a[3]), "r"(b[0]), "r"(b[1]));
}
__device__ __forceinline__ uint32_t smem_u32(const void* p) {
    uint32_t a;
    asm("{ .reg .u64 t; cvta.to.shared.u64 t, %1; cvt.u32.u64 %0, t; }" : "=r"(a) : "l"(p));
    return a;
}
#define CP_ASYNC16(dst, src) \
    asm volatile("cp.async.cg.shared.global [%0], [%1], 16;" :: "r"(dst), "l"(src) : "memory")
#define CP_COMMIT() asm volatile("cp.async.commit_group;" ::: "memory")
#define CP_WAIT0()  asm volatile("cp.async.wait_group 0;" ::: "memory")
#define CP_WAIT1()  asm volatile("cp.async.wait_group 1;" ::: "memory")

#define SCALE 0.08838834764831845f   /* 1/sqrt(128) */

// ---------------- prepass: tf32 rounding ----------------
__global__ void round_tf32(const float* __restrict__ in, float* __restrict__ out) {
    size_t i = ((size_t)blockIdx.x * blockDim.x + threadIdx.x) * 4;
    float4 v = *(const float4*)(in + i);
    v.x = tf32r(v.x); v.y = tf32r(v.y); v.z = tf32r(v.z); v.w = tf32r(v.w);
    *(float4*)(out + i) = v;
}

// ---------------- tf32 mma GEMM: CTA 128x256, 8 warps @ 64x64 ----------------
#define GBK 32
#define ALD 36                         /* A smem row stride (floats) */
#define BLD 264                        /* B smem row stride (floats) */
#define AS_F (128 * ALD)               /* 4608 */
#define BS_F (GBK * BLD)               /* 8448 */
#define STG_F (AS_F + BS_F)            /* 13056 */
#define GEMM_SMEM (3 * STG_F * 4)      /* 156672 B */

template <bool PROJ>
__global__ __launch_bounds__(256, 1) void gemm_k(
    const float* __restrict__ A,
    const float* __restrict__ B0, const float* __restrict__ B1, const float* __restrict__ B2,
    float* __restrict__ C0, float* __restrict__ C1,
    const float* __restrict__ bias, int M, int K)
{
    extern __shared__ float smg[];
    const int tid = threadIdx.x;
    const int wid = tid >> 5, l = tid & 31;
    const int lq = l >> 2, lr = l & 3;
    const int m0 = blockIdx.y * 128;
    const int n0 = blockIdx.x * 256;
    const int wm = (wid & 1) * 64, wn = (wid >> 1) * 64;
    const uint32_t smb = smem_u32(smg);

    const float* Bp; int ldB; float* Cp; int ldC; bool doscale = false;
    if (PROJ) {
        if (n0 < 2048)      { Bp = B0 + n0;          ldB = 2048; Cp = C0 + n0;                ldC = 2048; doscale = true; }
        else if (n0 < 2560) { Bp = B1 + (n0 - 2048); ldB = 512;  Cp = C1 + (n0 - 2048);       ldC = 1024; }
        else                { Bp = B2 + (n0 - 2560); ldB = 512;  Cp = C1 + (n0 - 2560 + 512); ldC = 1024; }
    } else { Bp = B0 + n0; ldB = 2048; Cp = C0 + n0; ldC = 2048; }

    const int kiters = K / GBK;

    float acc[4][8][4];
#pragma unroll
    for (int i = 0; i < 4; i++)
#pragma unroll
        for (int j = 0; j < 8; j++)
#pragma unroll
            for (int r = 0; r < 4; r++) acc[i][j][r] = 0.f;

#define G_LOAD(s, kc) do {                                                        \
        uint32_t _ab = smb + (s) * (STG_F * 4);                                   \
        uint32_t _bb = _ab + AS_F * 4;                                            \
        _Pragma("unroll")                                                         \
        for (int _i = 0; _i < 4; _i++) {                                          \
            int _e = tid + _i * 256, _r = _e >> 3, _kq = _e & 7;                  \
            CP_ASYNC16(_ab + (_r * ALD + _kq * 4) * 4,                            \
                (const void*)(A + (size_t)(m0 + _r) * K + (kc) * GBK + _kq * 4)); \
        }                                                                         \
        _Pragma("unroll")                                                         \
        for (int _i = 0; _i < 8; _i++) {                                          \
            int _e = tid + _i * 256, _r = _e >> 6, _cq = _e & 63;                 \
            CP_ASYNC16(_bb + (_r * BLD + _cq * 4) * 4,                            \
                (const void*)(Bp + (size_t)((kc) * GBK + _r) * ldB + _cq * 4));   \
        }                                                                         \
    } while (0)

    G_LOAD(0, 0); CP_COMMIT();
    G_LOAD(1, 1); CP_COMMIT();

    for (int it = 0; it < kiters; it++) {
        CP_WAIT1();
        __syncthreads();
        if (it + 2 < kiters) G_LOAD((it + 2) % 3, it + 2);
        CP_COMMIT();

        const float* As = smg + (it % 3) * STG_F;
        const float* Bs = As + AS_F;

#pragma unroll
        for (int ks = 0; ks < 4; ks++) {
            const int k8 = ks * 8;
            uint32_t af[4][4], bf[8][2];
#pragma unroll
            for (int mf = 0; mf < 4; mf++) {
                const float* p = As + (wm + mf * 16 + lq) * ALD + k8 + lr;
                af[mf][0] = __float_as_uint(p[0]);
                af[mf][1] = __float_as_uint(p[8 * ALD]);
                af[mf][2] = __float_as_uint(p[4]);
                af[mf][3] = __float_as_uint(p[8 * ALD + 4]);
            }
#pragma unroll
            for (int nf = 0; nf < 8; nf++) {
                const float* p = Bs + (k8 + lr) * BLD + wn + nf * 8 + lq;
                bf[nf][0] = __float_as_uint(p[0]);
                bf[nf][1] = __float_as_uint(p[4 * BLD]);
            }
#pragma unroll
            for (int mf = 0; mf < 4; mf++)
#pragma unroll
                for (int nf = 0; nf < 8; nf++)
                    mma_tf32(acc[mf][nf], af[mf], bf[nf]);
        }
        __syncthreads();
    }

    // epilogue
#pragma unroll
    for (int mf = 0; mf < 4; mf++) {
        const int row = m0 + wm + mf * 16 + lq;
#pragma unroll
        for (int nf = 0; nf < 8; nf++) {
            const int col = wn + nf * 8 + 2 * lr;
            float v0 = acc[mf][nf][0], v1 = acc[mf][nf][1];
            float v2 = acc[mf][nf][2], v3 = acc[mf][nf][3];
            if (PROJ) {
                if (doscale) { v0 *= SCALE; v1 *= SCALE; v2 *= SCALE; v3 *= SCALE; }
                v0 = tf32r(v0); v1 = tf32r(v1); v2 = tf32r(v2); v3 = tf32r(v3);
            } else {
                float2 b = *(const float2*)(bias + n0 + col);
                v0 += b.x; v1 += b.y; v2 += b.x; v3 += b.y;
            }
            *(float2*)(Cp + (size_t)row * ldC + col)       = make_float2(v0, v1);
            *(float2*)(Cp + (size_t)(row + 8) * ldC + col) = make_float2(v2, v3);
        }
    }
#undef G_LOAD
}

// ---------------- tf32 mma flash-attention ----------------
// 256 threads (8 warps). CTA: (batch, head) x 128 q-rows; warp: 16 rows.
// Q in registers; K/V double-buffered cp.async; P via padded smem.
#define KROW 132
#define VROW 136
#define PROW 76
#define KS_ST (64 * KROW)                       /* 8448 */
#define VS_ST (64 * VROW)                       /* 8704 */
#define PS_OFF (2 * KS_ST + 2 * VS_ST)          /* 34304 */
#define ATTN_SMEM ((PS_OFF + 8 * 16 * PROW) * 4)/* 176128 B */

__global__ __launch_bounds__(256, 1) void attn_mma(
    const float* __restrict__ Q, const float* __restrict__ KV,
    float* __restrict__ C)
{
    extern __shared__ float sm[];
    const int tid = threadIdx.x;
    const int wid = tid >> 5, l = tid & 31;
    const int lq = l >> 2, lr = l & 3;
    const int wq = wid * 16;

    const int qc = blockIdx.x;
    const int hh = blockIdx.y;
    const int bi = hh >> 4;
    const int gi = (hh >> 2) & 3;
    const int hi = hh & 3;
    const int qcol = (gi * HPG + hi) * HD;
    const int kcolK = gi * HD;
    const int kcolV = 512 + gi * HD;
    const size_t rowbase = (size_t)bi * SEQ;
    const int qbase = qc * 128;
    const uint32_t smb = smem_u32(sm);

    // ---- stage Q tile [128 x 128] into smem, then into registers ----
    for (int i = tid; i < 128 * 32; i += 256) {
        int r = i >> 5, c4 = (i & 31) << 2;
        *(float4*)&sm[r * KROW + c4] =
            *(const float4*)(Q + (rowbase + qbase + r) * (size_t)D_OUT + qcol + c4);
    }
    __syncthreads();
    uint32_t qf[16][4];
    {
        const float* qp = sm + (wq + lq) * KROW + lr;
#pragma unroll
        for (int kf = 0; kf < 16; kf++) {
            qf[kf][0] = __float_as_uint(qp[kf * 8]);
            qf[kf][1] = __float_as_uint(qp[8 * KROW + kf * 8]);
            qf[kf][2] = __float_as_uint(qp[kf * 8 + 4]);
            qf[kf][3] = __float_as_uint(qp[8 * KROW + kf * 8 + 4]);
        }
    }
    __syncthreads();   // all warps done reading Q before K/V overwrite

    float o[16][4];
#pragma unroll
    for (int i = 0; i < 16; i++)
#pragma unroll
        for (int r = 0; r < 4; r++) o[i][r] = 0.f;
    float m0 = -CUDART_INF_F, m1 = -CUDART_INF_F, l0 = 0.f, l1 = 0.f;

    float* myP = sm + PS_OFF + wid * 16 * PROW;
    const int gr0 = qbase + wq + lq;
    const int gr1 = gr0 + 8;
    const int jmax = 2 * qc + 1;

#define KV_LOAD(ss, jj) do {                                                     \
        uint32_t _kb = smb + (ss) * (KS_ST * 4);                                 \
        uint32_t _vb = smb + (2 * KS_ST + (ss) * VS_ST) * 4;                     \
        const float* _gk = KV + (rowbase + (jj) * 64) * KVD + kcolK;             \
        const float* _gv = KV + (rowbase + (jj) * 64) * KVD + kcolV;             \
        _Pragma("unroll")                                                        \
        for (int _u = 0; _u < 8; _u++) {                                         \
            int _e = tid + _u * 256, _r = _e >> 5, _c4 = (_e & 31) << 2;         \
            CP_ASYNC16(_kb + (_r * KROW + _c4) * 4,                              \
                       (const void*)(_gk + (size_t)_r * KVD + _c4));             \
            CP_ASYNC16(_vb + (_r * VROW + _c4) * 4,                              \
                       (const void*)(_gv + (size_t)_r * KVD + _c4));             \
        }                                                                        \
    } while (0)

    KV_LOAD(0, 0); CP_COMMIT();

    for (int j = 0; j <= jmax; j++) {
        CP_WAIT0();
        __syncthreads();
        if (j < jmax) KV_LOAD((j + 1) & 1, j + 1);
        CP_COMMIT();

        const int st = j & 1;
        const float* Ks = sm + st * KS_ST;
        const float* Vs = sm + 2 * KS_ST + st * VS_ST;
        const int kbase = j * 64;
        const bool active = (kbase <= qbase + wq + 15);

        if (active) {
            // S = Q @ K^T : 16x64
            float s[8][4];
#pragma unroll
            for (int nf = 0; nf < 8; nf++)
#pragma unroll
                for (int r = 0; r < 4; r++) s[nf][r] = 0.f;

#pragma unroll
            for (int kf = 0; kf < 16; kf++) {
#pragma unroll
                for (int nf = 0; nf < 8; nf++) {
                    const float* kp = Ks + (nf * 8 + lq) * KROW + kf * 8 + lr;
                    uint32_t b[2] = { __float_as_uint(kp[0]), __float_as_uint(kp[4]) };
                    mma_tf32(s[nf], qf[kf], b);
                }
            }

            // causal mask + row max
            const bool needmask = (kbase + 63 > qbase + wq);
            float mx0 = -CUDART_INF_F, mx1 = -CUDART_INF_F;
#pragma unroll
            for (int nf = 0; nf < 8; nf++) {
                if (needmask) {
                    const int c0 = kbase + nf * 8 + 2 * lr;
                    if (c0 > gr0)     s[nf][0] = -CUDART_INF_F;
                    if (c0 + 1 > gr0) s[nf][1] = -CUDART_INF_F;
                    if (c0 > gr1)     s[nf][2] = -CUDART_INF_F;
                    if (c0 + 1 > gr1) s[nf][3] = -CUDART_INF_F;
                }
                mx0 = fmaxf(mx0, fmaxf(s[nf][0], s[nf][1]));
                mx1 = fmaxf(mx1, fmaxf(s[nf][2], s[nf][3]));
            }
#pragma unroll
            for (int msk = 1; msk < 4; msk <<= 1) {
                mx0 = fmaxf(mx0, __shfl_xor_sync(0xffffffffu, mx0, msk));
                mx1 = fmaxf(mx1, __shfl_xor_sync(0xffffffffu, mx1, msk));
            }
            const float nm0 = fmaxf(m0, mx0);
            const float nm1 = fmaxf(m1, mx1);
            const float al0 = __expf(m0 - nm0);
            const float al1 = __expf(m1 - nm1);
            m0 = nm0; m1 = nm1;

            float sm0 = 0.f, sm1 = 0.f;
#pragma unroll
            for (int nf = 0; nf < 8; nf++) {
                float p0 = __expf(s[nf][0] - nm0);
                float p1 = __expf(s[nf][1] - nm0);
                float p2 = __expf(s[nf][2] - nm1);
                float p3 = __expf(s[nf][3] - nm1);
                sm0 += p0 + p1; sm1 += p2 + p3;
                float* pp = myP + lq * PROW + nf * 8 + 2 * lr;
                pp[0] = tf32r(p0); pp[1] = tf32r(p1);
                pp[8 * PROW] = tf32r(p2); pp[8 * PROW + 1] = tf32r(p3);
            }
#pragma unroll
            for (int msk = 1; msk < 4; msk <<= 1) {
                sm0 += __shfl_xor_sync(0xffffffffu, sm0, msk);
                sm1 += __shfl_xor_sync(0xffffffffu, sm1, msk);
            }
            l0 = l0 * al0 + sm0;
            l1 = l1 * al1 + sm1;

#pragma unroll
            for (int nf = 0; nf < 16; nf++) {
                o[nf][0] *= al0; o[nf][1] *= al0;
                o[nf][2] *= al1; o[nf][3] *= al1;
            }
            __syncwarp();

            // O += P @ V : 16x128, k over 64 keys
#pragma unroll
            for (int kf = 0; kf < 8; kf++) {
                const float* pp = myP + lq * PROW + kf * 8 + lr;
                uint32_t a[4] = { __float_as_uint(pp[0]),
                                  __float_as_uint(pp[8 * PROW]),
                                  __float_as_uint(pp[4]),
                                  __float_as_uint(pp[8 * PROW + 4]) };
#pragma unroll
                for (int nf = 0; nf < 16; nf++) {
                    const float* vp = Vs + (kf * 8 + lr) * VROW + nf * 8 + lq;
                    uint32_t b[2] = { __float_as_uint(vp[0]),
                                      __float_as_uint(vp[4 * VROW]) };
                    mma_tf32(o[nf], a, b);
                }
            }
            __syncwarp();
        }
    }

    // epilogue: normalize + tf32-round (feeds O-proj)
    const float inv0 = 1.f / l0, inv1 = 1.f / l1;
    const size_t r0 = rowbase + gr0, r1 = rowbase + gr1;
#pragma unroll
    for (int nf = 0; nf < 16; nf++) {
        const int col = qcol + nf * 8 + 2 * lr;
        *(float2*)(C + r0 * D_OUT + col) =
            make_float2(tf32r(o[nf][0] * inv0), tf32r(o[nf][1] * inv0));
        *(float2*)(C + r1 * D_OUT + col) =
            make_float2(tf32r(o[nf][2] * inv1), tf32r(o[nf][3] * inv1));
    }
#undef KV_LOAD
}

// ---------------------------------------------------------------------------
extern "C" void kernel_launch(void* const* d_in, const int* in_sizes, int n_in,
                              void* d_out, int out_size)
{
    const float* x  = (const float*)d_in[0];
    const float* Wq = (const float*)d_in[1];
    const float* Wk = (const float*)d_in[2];
    const float* Wv = (const float*)d_in[3];
    const float* Wo = (const float*)d_in[4];
    const float* bo = (const float*)d_in[5];

    const int M = in_sizes[0] / D_IN;   // 4096
    const int B = M / SEQ;              // 2

    float *Xr, *Wqr, *Wkr, *Wvr, *Wor, *Qp, *KVp, *Cp;
    cudaGetSymbolAddress((void**)&Xr,  g_X);
    cudaGetSymbolAddress((void**)&Wqr, g_Wq);
    cudaGetSymbolAddress((void**)&Wkr, g_Wk);
    cudaGetSymbolAddress((void**)&Wvr, g_Wv);
    cudaGetSymbolAddress((void**)&Wor, g_Wo);
    cudaGetSymbolAddress((void**)&Qp,  g_Q);
    cudaGetSymbolAddress((void**)&KVp, g_KV);
    cudaGetSymbolAddress((void**)&Cp,  g_C);

    cudaFuncSetAttribute(gemm_k<true>,
                         cudaFuncAttributeMaxDynamicSharedMemorySize, GEMM_SMEM);
    cudaFuncSetAttribute(gemm_k<false>,
                         cudaFuncAttributeMaxDynamicSharedMemorySize, GEMM_SMEM);
    cudaFuncSetAttribute(attn_mma,
                         cudaFuncAttributeMaxDynamicSharedMemorySize, ATTN_SMEM);

    // prepass: tf32-round x and weights (removes all mainloop cvts)
    round_tf32<<<(M * D_IN) / 1024, 256>>>(x, Xr);
    round_tf32<<<(D_IN * D_OUT) / 1024, 256>>>(Wq, Wqr);
    round_tf32<<<(D_IN * 512) / 1024, 256>>>(Wk, Wkr);
    round_tf32<<<(D_IN * 512) / 1024, 256>>>(Wv, Wvr);
    round_tf32<<<(D_OUT * D_OUT) / 1024, 256>>>(Wo, Wor);

    // fused QKV projection: N = 2048 (Q) + 512 (K) + 512 (V) = 3072
    gemm_k<true><<<dim3(12, M / 128), 256, GEMM_SMEM>>>(
        Xr, Wqr, Wkr, Wvr, Qp, KVp, nullptr, M, D_IN);

    attn_mma<<<dim3(SEQ / 128, B * 16), 256, ATTN_SMEM>>>(Qp, KVp, Cp);

    // output projection + bias
    gemm_k<false><<<dim3(8, M / 128), 256, GEMM_SMEM>>>(
        Cp, Wor, nullptr, nullptr, (float*)d_out, nullptr, bo, M, D_OUT);
}